// round 14
// baseline (speedup 1.0000x reference)
#include <cuda_runtime.h>
#include <cuda_fp16.h>
#include <cstdint>
#include <cstddef>

#define IN_DIM   1024
#define HID_DIM  512
#define OUT_DIM  1024
#define N_EXP    6
#define H3       3072
#define MAXB     32768

// ---------------- scratch (device globals; no allocation allowed) ----------
__device__ float  g_gate[(size_t)MAXB * N_EXP];
__device__ __half g_xh [(size_t)MAXB * IN_DIM];    // fp16(x)
__device__ __half g_w1 [(size_t)H3 * IN_DIM];      // fp16(W1^T) [3072,1024] K contig
__device__ __half g_w2 [(size_t)OUT_DIM * H3];     // fp16(W2^T) [1024,3072] K contig
__device__ __half g_hs [(size_t)MAXB * H3];        // fp16 hidden

// ---------------- helpers ---------------------------------------------------
__device__ __forceinline__ uint32_t smem_u32(const void* p) {
    uint32_t a;
    asm("{ .reg .u64 t; cvta.to.shared.u64 t, %1; cvt.u32.u64 %0, t; }" : "=r"(a) : "l"(p));
    return a;
}
__device__ __forceinline__ void cp16(uint32_t dst, const void* src) {
    asm volatile("cp.async.cg.shared.global [%0], [%1], 16;" :: "r"(dst), "l"(src));
}
__device__ __forceinline__ void cp_commit() {
    asm volatile("cp.async.commit_group;" ::: "memory");
}
template <int N>
__device__ __forceinline__ void cp_wait() {
    asm volatile("cp.async.wait_group %0;" :: "n"(N) : "memory");
}
__device__ __forceinline__ void ldsm4(uint32_t* r, uint32_t addr) {
    asm volatile("ldmatrix.sync.aligned.m8n8.x4.shared.b16 {%0,%1,%2,%3}, [%4];"
                 : "=r"(r[0]), "=r"(r[1]), "=r"(r[2]), "=r"(r[3]) : "r"(addr));
}
__device__ __forceinline__ void mma_f16(float* c, const uint32_t* a, const uint32_t* b) {
    asm volatile(
        "mma.sync.aligned.m16n8k16.row.col.f32.f16.f16.f32 "
        "{%0,%1,%2,%3}, {%4,%5,%6,%7}, {%8,%9}, {%0,%1,%2,%3};"
        : "+f"(c[0]), "+f"(c[1]), "+f"(c[2]), "+f"(c[3])
        : "r"(a[0]), "r"(a[1]), "r"(a[2]), "r"(a[3]), "r"(b[0]), "r"(b[1]));
}
// 64B rows, 16B chunks, xor-swizzle (conflict-free ldmatrix)
__device__ __forceinline__ int sw_off(int row, int chunk) {
    return row * 64 + ((chunk ^ ((row >> 1) & 3)) << 4);
}
__device__ __forceinline__ uint32_t pk_h2(float v0, float v1) {
    __half2 h = __halves2half2(__float2half_rn(v0), __float2half_rn(v1));
    return *reinterpret_cast<uint32_t*>(&h);
}

// ---------------- fused gate + fp16 quantize of x ---------------------------
__global__ __launch_bounds__(256) void gate_split_kernel(
    const float* __restrict__ x,
    const float* __restrict__ g2w, const float* __restrict__ g2b,
    const float* __restrict__ g3w, const float* __restrict__ g3b,
    float* __restrict__ gate, __half* __restrict__ xh, int B)
{
    int row  = (blockIdx.x * 256 + threadIdx.x) >> 5;
    int lane = threadIdx.x & 31;
    if (row >= B) return;

    const float4* xr = reinterpret_cast<const float4*>(x + (size_t)row * IN_DIM);
    float a0 = 0.f, a1 = 0.f, a2 = 0.f, a3 = 0.f;
    #pragma unroll
    for (int j = 0; j < 8; ++j) {
        int i = lane + j * 32;
        float4 v = xr[i];
        int k = i * 4;
        a0 = fmaf(v.x, g2w[k], fmaf(v.y, g2w[k+1], fmaf(v.z, g2w[k+2], fmaf(v.w, g2w[k+3], a0))));
        a1 = fmaf(v.x, g3w[k*3+0], fmaf(v.y, g3w[(k+1)*3+0], fmaf(v.z, g3w[(k+2)*3+0], fmaf(v.w, g3w[(k+3)*3+0], a1))));
        a2 = fmaf(v.x, g3w[k*3+1], fmaf(v.y, g3w[(k+1)*3+1], fmaf(v.z, g3w[(k+2)*3+1], fmaf(v.w, g3w[(k+3)*3+1], a2))));
        a3 = fmaf(v.x, g3w[k*3+2], fmaf(v.y, g3w[(k+1)*3+2], fmaf(v.z, g3w[(k+2)*3+2], fmaf(v.w, g3w[(k+3)*3+2], a3))));
        *reinterpret_cast<uint2*>(xh + (size_t)row * IN_DIM + k) =
            make_uint2(pk_h2(v.x, v.y), pk_h2(v.z, v.w));
    }
    #pragma unroll
    for (int off = 16; off > 0; off >>= 1) {
        a0 += __shfl_down_sync(0xffffffffu, a0, off);
        a1 += __shfl_down_sync(0xffffffffu, a1, off);
        a2 += __shfl_down_sync(0xffffffffu, a2, off);
        a3 += __shfl_down_sync(0xffffffffu, a3, off);
    }
    if (lane == 0) {
        float alpha = 1.f / (1.f + expf(-(a0 + g2b[0])));
        float l0 = a1 + g3b[0], l1 = a2 + g3b[1], l2 = a3 + g3b[2];
        float m = fmaxf(l0, fmaxf(l1, l2));
        float e0 = expf(l0 - m), e1 = expf(l1 - m), e2 = expf(l2 - m);
        float inv = 1.f / (e0 + e1 + e2);
        float p0 = e0 * inv, p1 = e1 * inv, p2 = e2 * inv, ga = 1.f - alpha;
        float* o = gate + (size_t)row * N_EXP;
        o[0] = ga * p0;    o[1] = ga * p1;    o[2] = ga * p2;
        o[3] = alpha * p0; o[4] = alpha * p1; o[5] = alpha * p2;
    }
}

// -------- transpose + quantize: src[R,C] fp32 -> dst[C,R] fp16 --------------
__global__ void transquant_kernel(const float* __restrict__ src,
                                  __half* __restrict__ dst, int R, int C)
{
    __shared__ float t[32][33];
    size_t zoff = (size_t)blockIdx.z * R * C;
    int c0 = blockIdx.x * 32, r0 = blockIdx.y * 32;
    int tx = threadIdx.x, ty = threadIdx.y;          // 32 x 8
    #pragma unroll
    for (int i = 0; i < 4; ++i)
        t[ty + i*8][tx] = src[zoff + (size_t)(r0 + ty + i*8) * C + c0 + tx];
    __syncthreads();
    #pragma unroll
    for (int i = 0; i < 4; ++i) {
        int c = c0 + ty + i*8, r = r0 + tx;
        dst[zoff + (size_t)c * R + r] = __float2half_rn(t[tx][ty + i*8]);
    }
}

// ================== 1-pass fp16 GEMM, CTA 128x256, warp 64x64 ===============
// 8 warps (2M x 4N), warp tile 64x64 (acc = 128 fp32), BK=64, 1 CTA/SM,
// 2-stage double buffer (48KB/stage = A 16K | B 32K; 96KB total).
// Stage layout: A: [sub k32][row 0..127][64B sw]; B: [sub k32][row 0..255].
#define BM 128
#define BN 256
#define BK 64
#define STAGE_BYTES 49152
#define SMEM_TOTAL (2 * STAGE_BYTES)

// Load one 48KB stage (3072 16B chunks; 12 per thread). Plain function, no lambda.
template <int K>
__device__ __forceinline__ void load_stage_fn(
    uint32_t sb, const __half* __restrict__ Asrc,
    const __half* __restrict__ Bsrc, int k0, int tid)
{
    #pragma unroll
    for (int j = 0; j < 4; ++j) {            // A: 1024 chunks
        int idx = tid + j * 256;
        int sub = idx >> 9, ii = idx & 511;
        int row = ii >> 2, c = ii & 3;
        cp16(sb + sub * 8192 + sw_off(row, c),
             Asrc + (size_t)row * K + k0 + sub * 32 + c * 8);
    }
    #pragma unroll
    for (int j = 0; j < 8; ++j) {            // B: 2048 chunks
        int idx = tid + j * 256;
        int sub = idx >> 10, ii = idx & 1023;
        int row = ii >> 2, c = ii & 3;
        cp16(sb + 16384 + sub * 16384 + sw_off(row, c),
             Bsrc + (size_t)row * K + k0 + sub * 32 + c * 8);
    }
    cp_commit();
}

template <int K, bool FIRST>
__global__ __launch_bounds__(256, 1) void gemm_mma(
    const __half* __restrict__ A, const __half* __restrict__ Bw,
    const float* __restrict__ bias, const float* __restrict__ gate,
    __half* __restrict__ Chs, float* __restrict__ Cf)
{
    extern __shared__ char smem[];
    const uint32_t sbase = smem_u32(smem);
    const int tid  = threadIdx.x;
    const int wid  = tid >> 5;
    const int lane = tid & 31;
    const int mBlk = blockIdx.y * BM;
    const int nBlk = blockIdx.x * BN;
    const int wm = (wid >> 2) * 64;      // 2 warps in M
    const int wn = (wid & 3) * 64;       // 4 warps in N
    constexpr int NK = K / BK;

    const __half* Asrc = A  + (size_t)mBlk * K;
    const __half* Bsrc = Bw + (size_t)nBlk * K;

    float acc[4][8][4];
    #pragma unroll
    for (int i = 0; i < 4; ++i)
        #pragma unroll
        for (int j = 0; j < 8; ++j)
            #pragma unroll
            for (int q = 0; q < 4; ++q) acc[i][j][q] = 0.f;

    // prologue: stage 0 -> slot 0
    load_stage_fn<K>(sbase, Asrc, Bsrc, 0, tid);

    const int rA = wm + (lane & 15);
    const int rB = wn + ((lane >> 4) << 3) + (lane & 7);
    const int cAoff = lane >> 4;
    const int cBoff = (lane >> 3) & 1;

    #pragma unroll 2
    for (int s = 0; s < NK; ++s) {
        cp_wait<0>();
        __syncthreads();
        const uint32_t sb = sbase + (s & 1) * STAGE_BYTES;

        // next stage into the other slot (overlaps this iter's MMAs)
        if (s + 1 < NK)
            load_stage_fn<K>(sbase + ((s + 1) & 1) * STAGE_BYTES,
                             Asrc, Bsrc, (s + 1) * BK, tid);

        #pragma unroll
        for (int kk = 0; kk < 4; ++kk) {
            uint32_t Af[16], Bf[16];
            {
                const uint32_t baseA = sb + (kk >> 1) * 8192;
                const int ca = (kk & 1) * 2 + cAoff;
                #pragma unroll
                for (int mi = 0; mi < 4; ++mi)
                    ldsm4(Af + mi * 4, baseA + sw_off(rA + 16 * mi, ca));
            }
            {
                const uint32_t baseB = sb + 16384 + (kk >> 1) * 16384;
                const int cb = (kk & 1) * 2 + cBoff;
                #pragma unroll
                for (int jp = 0; jp < 4; ++jp) {
                    uint32_t t[4];
                    ldsm4(t, baseB + sw_off(rB + 16 * jp, cb));
                    Bf[(2 * jp) * 2]         = t[0];
                    Bf[(2 * jp) * 2 + 1]     = t[1];
                    Bf[(2 * jp + 1) * 2]     = t[2];
                    Bf[(2 * jp + 1) * 2 + 1] = t[3];
                }
            }
            #pragma unroll
            for (int mi = 0; mi < 4; ++mi)
                #pragma unroll
                for (int nj = 0; nj < 8; ++nj)
                    mma_f16(acc[mi][nj], Af + mi * 4, Bf + nj * 2);
        }
    }

    // ---- epilogue ----
    if constexpr (FIRST) {
        const int e = nBlk >> 9;
        float bcol[16];
        #pragma unroll
        for (int nj = 0; nj < 8; ++nj) {
            const int col = nBlk + wn + 8 * nj + 2 * (lane & 3);
            const int bc = e * HID_DIM + (col & (HID_DIM - 1));
            bcol[2*nj]   = bias[bc];
            bcol[2*nj+1] = bias[bc + 1];
        }
        #pragma unroll
        for (int mi = 0; mi < 4; ++mi)
            #pragma unroll
            for (int h = 0; h < 2; ++h) {
                const int row = mBlk + wm + 16 * mi + (lane >> 2) + 8 * h;
                const float g = gate[(size_t)row * N_EXP + e];
                #pragma unroll
                for (int nj = 0; nj < 8; ++nj) {
                    const int col = nBlk + wn + 8 * nj + 2 * (lane & 3);
                    float v0 = fmaxf(acc[mi][nj][2*h]   + bcol[2*nj],   0.f) * g;
                    float v1 = fmaxf(acc[mi][nj][2*h+1] + bcol[2*nj+1], 0.f) * g;
                    *reinterpret_cast<uint32_t*>(Chs + (size_t)row * H3 + col) = pk_h2(v0, v1);
                }
            }
    } else {
        #pragma unroll
        for (int mi = 0; mi < 4; ++mi)
            #pragma unroll
            for (int h = 0; h < 2; ++h) {
                const int row = mBlk + wm + 16 * mi + (lane >> 2) + 8 * h;
                const float2* gp = reinterpret_cast<const float2*>(gate + (size_t)row * N_EXP);
                float2 gA = gp[0], gB = gp[1], gC = gp[2];
                float gw[N_EXP] = {gA.x, gA.y, gB.x, gB.y, gC.x, gC.y};
                #pragma unroll
                for (int nj = 0; nj < 8; ++nj) {
                    const int col = nBlk + wn + 8 * nj + 2 * (lane & 3);
                    float v0 = acc[mi][nj][2*h];
                    float v1 = acc[mi][nj][2*h+1];
                    #pragma unroll
                    for (int q = 0; q < N_EXP; ++q) {
                        v0 = fmaf(gw[q], bias[q * OUT_DIM + col],     v0);
                        v1 = fmaf(gw[q], bias[q * OUT_DIM + col + 1], v1);
                    }
                    *reinterpret_cast<float2*>(Cf + (size_t)row * OUT_DIM + col) = make_float2(v0, v1);
                }
            }
    }
}

// ---------------------------------------------------------------------------
extern "C" void kernel_launch(void* const* d_in, const int* in_sizes, int n_in,
                              void* d_out, int out_size)
{
    const float* x   = (const float*)d_in[0];
    const float* g2w = (const float*)d_in[1];
    const float* g2b = (const float*)d_in[2];
    const float* g3w = (const float*)d_in[3];
    const float* g3b = (const float*)d_in[4];
    const float* w1  = (const float*)d_in[5];
    const float* b1  = (const float*)d_in[6];
    const float* w2  = (const float*)d_in[7];
    const float* b2  = (const float*)d_in[8];
    float* out = (float*)d_out;

    const int B = in_sizes[0] / IN_DIM;   // 32768

    float* gate;
    __half *xh, *w1q, *w2q, *hs;
    cudaGetSymbolAddress((void**)&gate, g_gate);
    cudaGetSymbolAddress((void**)&xh, g_xh);
    cudaGetSymbolAddress((void**)&w1q, g_w1);
    cudaGetSymbolAddress((void**)&w2q, g_w2);
    cudaGetSymbolAddress((void**)&hs, g_hs);

    cudaFuncSetAttribute(gemm_mma<IN_DIM, true>,
                         cudaFuncAttributeMaxDynamicSharedMemorySize, SMEM_TOTAL);
    cudaFuncSetAttribute(gemm_mma<H3, false>,
                         cudaFuncAttributeMaxDynamicSharedMemorySize, SMEM_TOTAL);

    // 1) gate + fp16 quantize x
    gate_split_kernel<<<(B + 7) / 8, 256>>>(x, g2w, g2b, g3w, g3b, gate, xh, B);

    // 2) transpose + fp16 quantize weights
    transquant_kernel<<<dim3(HID_DIM/32, IN_DIM/32, N_EXP), dim3(32, 8)>>>(w1, w1q, IN_DIM, HID_DIM);
    transquant_kernel<<<dim3(OUT_DIM/32, H3/32, 1),        dim3(32, 8)>>>(w2, w2q, H3, OUT_DIM);

    // 3) hs = fp16(relu(x @ W1 + b1) * gate)   [B,3072]
    gemm_mma<IN_DIM, true><<<dim3(H3/BN, B/BM), 256, SMEM_TOTAL>>>(
        xh, w1q, b1, gate, hs, nullptr);

    // 4) out = hs @ W2 + gate @ b2             [B,1024]
    gemm_mma<H3, false><<<dim3(OUT_DIM/BN, B/BM), 256, SMEM_TOTAL>>>(
        hs, w2q, b2, gate, nullptr, out);
}

// round 15
// speedup vs baseline: 1.0937x; 1.0937x over previous
#include <cuda_runtime.h>
#include <cuda_fp16.h>
#include <cstdint>
#include <cstddef>

#define IN_DIM   1024
#define HID_DIM  512
#define OUT_DIM  1024
#define N_EXP    6
#define H3       3072
#define MAXB     32768

// ---------------- scratch (device globals; no allocation allowed) ----------
__device__ float  g_gate[(size_t)MAXB * N_EXP];
__device__ __half g_xh [(size_t)MAXB * IN_DIM];    // fp16(x)
__device__ __half g_w1 [(size_t)H3 * IN_DIM];      // fp16(W1^T) [3072,1024] K contig
__device__ __half g_w2 [(size_t)OUT_DIM * H3];     // fp16(W2^T) [1024,3072] K contig
__device__ __half g_hs [(size_t)MAXB * H3];        // fp16 hidden

// ---------------- helpers ---------------------------------------------------
__device__ __forceinline__ uint32_t smem_u32(const void* p) {
    uint32_t a;
    asm("{ .reg .u64 t; cvta.to.shared.u64 t, %1; cvt.u32.u64 %0, t; }" : "=r"(a) : "l"(p));
    return a;
}
__device__ __forceinline__ void cp16(uint32_t dst, const void* src) {
    asm volatile("cp.async.cg.shared.global [%0], [%1], 16;" :: "r"(dst), "l"(src));
}
__device__ __forceinline__ void cp_commit() {
    asm volatile("cp.async.commit_group;" ::: "memory");
}
template <int N>
__device__ __forceinline__ void cp_wait() {
    asm volatile("cp.async.wait_group %0;" :: "n"(N) : "memory");
}
__device__ __forceinline__ void ldsm4(uint32_t* r, uint32_t addr) {
    asm volatile("ldmatrix.sync.aligned.m8n8.x4.shared.b16 {%0,%1,%2,%3}, [%4];"
                 : "=r"(r[0]), "=r"(r[1]), "=r"(r[2]), "=r"(r[3]) : "r"(addr));
}
__device__ __forceinline__ void mma_f16(float* c, const uint32_t* a, const uint32_t* b) {
    asm volatile(
        "mma.sync.aligned.m16n8k16.row.col.f32.f16.f16.f32 "
        "{%0,%1,%2,%3}, {%4,%5,%6,%7}, {%8,%9}, {%0,%1,%2,%3};"
        : "+f"(c[0]), "+f"(c[1]), "+f"(c[2]), "+f"(c[3])
        : "r"(a[0]), "r"(a[1]), "r"(a[2]), "r"(a[3]), "r"(b[0]), "r"(b[1]));
}
// 64B rows, 16B chunks, xor-swizzle (conflict-free ldmatrix)
__device__ __forceinline__ int sw_off(int row, int chunk) {
    return row * 64 + ((chunk ^ ((row >> 1) & 3)) << 4);
}
__device__ __forceinline__ uint32_t pk_h2(float v0, float v1) {
    __half2 h = __halves2half2(__float2half_rn(v0), __float2half_rn(v1));
    return *reinterpret_cast<uint32_t*>(&h);
}

// ---------------- fused gate + fp16 quantize of x ---------------------------
__global__ __launch_bounds__(256) void gate_split_kernel(
    const float* __restrict__ x,
    const float* __restrict__ g2w, const float* __restrict__ g2b,
    const float* __restrict__ g3w, const float* __restrict__ g3b,
    float* __restrict__ gate, __half* __restrict__ xh, int B)
{
    int row  = (blockIdx.x * 256 + threadIdx.x) >> 5;
    int lane = threadIdx.x & 31;
    if (row >= B) return;

    const float4* xr = reinterpret_cast<const float4*>(x + (size_t)row * IN_DIM);
    float a0 = 0.f, a1 = 0.f, a2 = 0.f, a3 = 0.f;
    #pragma unroll
    for (int j = 0; j < 8; ++j) {
        int i = lane + j * 32;
        float4 v = xr[i];
        int k = i * 4;
        a0 = fmaf(v.x, g2w[k], fmaf(v.y, g2w[k+1], fmaf(v.z, g2w[k+2], fmaf(v.w, g2w[k+3], a0))));
        a1 = fmaf(v.x, g3w[k*3+0], fmaf(v.y, g3w[(k+1)*3+0], fmaf(v.z, g3w[(k+2)*3+0], fmaf(v.w, g3w[(k+3)*3+0], a1))));
        a2 = fmaf(v.x, g3w[k*3+1], fmaf(v.y, g3w[(k+1)*3+1], fmaf(v.z, g3w[(k+2)*3+1], fmaf(v.w, g3w[(k+3)*3+1], a2))));
        a3 = fmaf(v.x, g3w[k*3+2], fmaf(v.y, g3w[(k+1)*3+2], fmaf(v.z, g3w[(k+2)*3+2], fmaf(v.w, g3w[(k+3)*3+2], a3))));
        *reinterpret_cast<uint2*>(xh + (size_t)row * IN_DIM + k) =
            make_uint2(pk_h2(v.x, v.y), pk_h2(v.z, v.w));
    }
    #pragma unroll
    for (int off = 16; off > 0; off >>= 1) {
        a0 += __shfl_down_sync(0xffffffffu, a0, off);
        a1 += __shfl_down_sync(0xffffffffu, a1, off);
        a2 += __shfl_down_sync(0xffffffffu, a2, off);
        a3 += __shfl_down_sync(0xffffffffu, a3, off);
    }
    if (lane == 0) {
        float alpha = 1.f / (1.f + expf(-(a0 + g2b[0])));
        float l0 = a1 + g3b[0], l1 = a2 + g3b[1], l2 = a3 + g3b[2];
        float m = fmaxf(l0, fmaxf(l1, l2));
        float e0 = expf(l0 - m), e1 = expf(l1 - m), e2 = expf(l2 - m);
        float inv = 1.f / (e0 + e1 + e2);
        float p0 = e0 * inv, p1 = e1 * inv, p2 = e2 * inv, ga = 1.f - alpha;
        float* o = gate + (size_t)row * N_EXP;
        o[0] = ga * p0;    o[1] = ga * p1;    o[2] = ga * p2;
        o[3] = alpha * p0; o[4] = alpha * p1; o[5] = alpha * p2;
    }
}

// -------- transpose + quantize: src[R,C] fp32 -> dst[C,R] fp16 --------------
__global__ void transquant_kernel(const float* __restrict__ src,
                                  __half* __restrict__ dst, int R, int C)
{
    __shared__ float t[32][33];
    size_t zoff = (size_t)blockIdx.z * R * C;
    int c0 = blockIdx.x * 32, r0 = blockIdx.y * 32;
    int tx = threadIdx.x, ty = threadIdx.y;          // 32 x 8
    #pragma unroll
    for (int i = 0; i < 4; ++i)
        t[ty + i*8][tx] = src[zoff + (size_t)(r0 + ty + i*8) * C + c0 + tx];
    __syncthreads();
    #pragma unroll
    for (int i = 0; i < 4; ++i) {
        int c = c0 + ty + i*8, r = r0 + tx;
        dst[zoff + (size_t)c * R + r] = __float2half_rn(t[tx][ty + i*8]);
    }
}

// ======= 1-pass fp16 GEMM: CTA 128x128, 4 warps (2Mx2N), warp 64x64 =========
// 128 threads, BK=64 (4 k16/iter), fp32 acc (128 regs), 3-stage pipeline
// (32KB/stage = A 16K | B 16K; 96KB/CTA, 2 CTAs/SM). Co-resident CTAs give
// independent barrier domains; warp 64x64 gives 32 MMAs per 8 ldsm.
#define BM 128
#define BN 128
#define BK 64
#define STAGES 3
#define STAGE_BYTES 32768
#define SMEM_TOTAL (STAGES * STAGE_BYTES)

// Load one 32KB stage: 2048 16B chunks, 128 threads -> 16 per thread.
template <int K>
__device__ __forceinline__ void load_stage_fn(
    uint32_t sb, const __half* __restrict__ Asrc,
    const __half* __restrict__ Bsrc, int k0, int tid)
{
    #pragma unroll
    for (int j = 0; j < 8; ++j) {            // A: 1024 chunks
        int idx = tid + j * 128;
        int sub = idx >> 9, ii = idx & 511;
        int row = ii >> 2, c = ii & 3;
        cp16(sb + sub * 8192 + sw_off(row, c),
             Asrc + (size_t)row * K + k0 + sub * 32 + c * 8);
    }
    #pragma unroll
    for (int j = 0; j < 8; ++j) {            // B: 1024 chunks
        int idx = tid + j * 128;
        int sub = idx >> 9, ii = idx & 511;
        int row = ii >> 2, c = ii & 3;
        cp16(sb + 16384 + sub * 8192 + sw_off(row, c),
             Bsrc + (size_t)row * K + k0 + sub * 32 + c * 8);
    }
    cp_commit();
}

template <int K, bool FIRST>
__global__ __launch_bounds__(128, 2) void gemm_mma(
    const __half* __restrict__ A, const __half* __restrict__ Bw,
    const float* __restrict__ bias, const float* __restrict__ gate,
    __half* __restrict__ Chs, float* __restrict__ Cf)
{
    extern __shared__ char smem[];
    const uint32_t sbase = smem_u32(smem);
    const int tid  = threadIdx.x;
    const int wid  = tid >> 5;
    const int lane = tid & 31;
    const int mBlk = blockIdx.y * BM;
    const int nBlk = blockIdx.x * BN;
    const int wm = (wid >> 1) * 64;      // 2 warps in M
    const int wn = (wid & 1) * 64;       // 2 warps in N
    constexpr int NK = K / BK;

    const __half* Asrc = A  + (size_t)mBlk * K;
    const __half* Bsrc = Bw + (size_t)nBlk * K;

    float acc[4][8][4];
    #pragma unroll
    for (int i = 0; i < 4; ++i)
        #pragma unroll
        for (int j = 0; j < 8; ++j)
            #pragma unroll
            for (int q = 0; q < 4; ++q) acc[i][j][q] = 0.f;

    // prologue: stages 0..1
    load_stage_fn<K>(sbase, Asrc, Bsrc, 0, tid);
    load_stage_fn<K>(sbase + STAGE_BYTES, Asrc, Bsrc, BK, tid);

    const int rA = wm + (lane & 15);
    const int rB = wn + ((lane >> 4) << 3) + (lane & 7);
    const int cAoff = lane >> 4;
    const int cBoff = (lane >> 3) & 1;

    #pragma unroll 3
    for (int s = 0; s < NK; ++s) {
        cp_wait<STAGES - 2>();
        __syncthreads();
        const uint32_t sb = sbase + (s % STAGES) * STAGE_BYTES;

        // next stage into slot (s+2)%3 (just freed by the sync above)
        if (s + STAGES - 1 < NK)
            load_stage_fn<K>(sbase + ((s + STAGES - 1) % STAGES) * STAGE_BYTES,
                             Asrc, Bsrc, (s + STAGES - 1) * BK, tid);
        else cp_commit();

        #pragma unroll
        for (int kk = 0; kk < 4; ++kk) {
            uint32_t Af[16], Bf[16];
            {
                const uint32_t baseA = sb + (kk >> 1) * 8192;
                const int ca = (kk & 1) * 2 + cAoff;
                #pragma unroll
                for (int mi = 0; mi < 4; ++mi)
                    ldsm4(Af + mi * 4, baseA + sw_off(rA + 16 * mi, ca));
            }
            {
                const uint32_t baseB = sb + 16384 + (kk >> 1) * 8192;
                const int cb = (kk & 1) * 2 + cBoff;
                #pragma unroll
                for (int jp = 0; jp < 4; ++jp) {
                    uint32_t t[4];
                    ldsm4(t, baseB + sw_off(rB + 16 * jp, cb));
                    Bf[(2 * jp) * 2]         = t[0];
                    Bf[(2 * jp) * 2 + 1]     = t[1];
                    Bf[(2 * jp + 1) * 2]     = t[2];
                    Bf[(2 * jp + 1) * 2 + 1] = t[3];
                }
            }
            #pragma unroll
            for (int mi = 0; mi < 4; ++mi)
                #pragma unroll
                for (int nj = 0; nj < 8; ++nj)
                    mma_f16(acc[mi][nj], Af + mi * 4, Bf + nj * 2);
        }
    }

    // ---- epilogue ----
    if constexpr (FIRST) {
        const int e = nBlk >> 9;
        float bcol[16];
        #pragma unroll
        for (int nj = 0; nj < 8; ++nj) {
            const int col = nBlk + wn + 8 * nj + 2 * (lane & 3);
            const int bc = e * HID_DIM + (col & (HID_DIM - 1));
            bcol[2*nj]   = bias[bc];
            bcol[2*nj+1] = bias[bc + 1];
        }
        #pragma unroll
        for (int mi = 0; mi < 4; ++mi)
            #pragma unroll
            for (int h = 0; h < 2; ++h) {
                const int row = mBlk + wm + 16 * mi + (lane >> 2) + 8 * h;
                const float g = gate[(size_t)row * N_EXP + e];
                #pragma unroll
                for (int nj = 0; nj < 8; ++nj) {
                    const int col = nBlk + wn + 8 * nj + 2 * (lane & 3);
                    float v0 = fmaxf(acc[mi][nj][2*h]   + bcol[2*nj],   0.f) * g;
                    float v1 = fmaxf(acc[mi][nj][2*h+1] + bcol[2*nj+1], 0.f) * g;
                    *reinterpret_cast<uint32_t*>(Chs + (size_t)row * H3 + col) = pk_h2(v0, v1);
                }
            }
    } else {
        #pragma unroll
        for (int mi = 0; mi < 4; ++mi)
            #pragma unroll
            for (int h = 0; h < 2; ++h) {
                const int row = mBlk + wm + 16 * mi + (lane >> 2) + 8 * h;
                const float2* gp = reinterpret_cast<const float2*>(gate + (size_t)row * N_EXP);
                float2 gA = gp[0], gB = gp[1], gC = gp[2];
                float gw[N_EXP] = {gA.x, gA.y, gB.x, gB.y, gC.x, gC.y};
                #pragma unroll
                for (int nj = 0; nj < 8; ++nj) {
                    const int col = nBlk + wn + 8 * nj + 2 * (lane & 3);
                    float v0 = acc[mi][nj][2*h];
                    float v1 = acc[mi][nj][2*h+1];
                    #pragma unroll
                    for (int q = 0; q < N_EXP; ++q) {
                        v0 = fmaf(gw[q], bias[q * OUT_DIM + col],     v0);
                        v1 = fmaf(gw[q], bias[q * OUT_DIM + col + 1], v1);
                    }
                    *reinterpret_cast<float2*>(Cf + (size_t)row * OUT_DIM + col) = make_float2(v0, v1);
                }
            }
    }
}

// ---------------------------------------------------------------------------
extern "C" void kernel_launch(void* const* d_in, const int* in_sizes, int n_in,
                              void* d_out, int out_size)
{
    const float* x   = (const float*)d_in[0];
    const float* g2w = (const float*)d_in[1];
    const float* g2b = (const float*)d_in[2];
    const float* g3w = (const float*)d_in[3];
    const float* g3b = (const float*)d_in[4];
    const float* w1  = (const float*)d_in[5];
    const float* b1  = (const float*)d_in[6];
    const float* w2  = (const float*)d_in[7];
    const float* b2  = (const float*)d_in[8];
    float* out = (float*)d_out;

    const int B = in_sizes[0] / IN_DIM;   // 32768

    float* gate;
    __half *xh, *w1q, *w2q, *hs;
    cudaGetSymbolAddress((void**)&gate, g_gate);
    cudaGetSymbolAddress((void**)&xh, g_xh);
    cudaGetSymbolAddress((void**)&w1q, g_w1);
    cudaGetSymbolAddress((void**)&w2q, g_w2);
    cudaGetSymbolAddress((void**)&hs, g_hs);

    cudaFuncSetAttribute(gemm_mma<IN_DIM, true>,
                         cudaFuncAttributeMaxDynamicSharedMemorySize, SMEM_TOTAL);
    cudaFuncSetAttribute(gemm_mma<H3, false>,
                         cudaFuncAttributeMaxDynamicSharedMemorySize, SMEM_TOTAL);

    // 1) gate + fp16 quantize x
    gate_split_kernel<<<(B + 7) / 8, 256>>>(x, g2w, g2b, g3w, g3b, gate, xh, B);

    // 2) transpose + fp16 quantize weights
    transquant_kernel<<<dim3(HID_DIM/32, IN_DIM/32, N_EXP), dim3(32, 8)>>>(w1, w1q, IN_DIM, HID_DIM);
    transquant_kernel<<<dim3(OUT_DIM/32, H3/32, 1),        dim3(32, 8)>>>(w2, w2q, H3, OUT_DIM);

    // 3) hs = fp16(relu(x @ W1 + b1) * gate)   [B,3072]
    gemm_mma<IN_DIM, true><<<dim3(H3/BN, B/BM), 128, SMEM_TOTAL>>>(
        xh, w1q, b1, gate, hs, nullptr);

    // 4) out = hs @ W2 + gate @ b2             [B,1024]
    gemm_mma<H3, false><<<dim3(OUT_DIM/BN, B/BM), 128, SMEM_TOTAL>>>(
        hs, w2q, b2, gate, nullptr, out);
}